// round 5
// baseline (speedup 1.0000x reference)
#include <cuda_runtime.h>
#include <math.h>

// Problem constants
constexpr int BB = 64;     // batch
constexpr int SS = 2048;   // seq len
constexpr int II = 256;    // input dim
constexpr int HH = 512;    // hidden dim
constexpr int GG = 1536;   // 3*H

// ---------------- device scratch (no allocations allowed) ----------------
__device__ float g_xproj[(size_t)BB * SS * GG];  // 805 MB precomputed input projections
__device__ float g_hA[BB * HH];
__device__ float g_hB[BB * HH];
__device__ unsigned g_cnt;            // zero-init, returns to zero each run
__device__ volatile unsigned g_gen;   // monotonic generation counter

// ---------------- Phase 1: x_proj = x @ W + bias ----------------
// M=131072, K=256, N=1536. 128x128 tile, BK=16, 8x8 per thread, 256 threads.
__global__ __launch_bounds__(256) void gemm_xw(const float* __restrict__ A,
                                               const float* __restrict__ Bm,
                                               const float* __restrict__ bias) {
    __shared__ float As[16 * 132];   // transposed, padded
    __shared__ float Bs[16 * 132];
    const int tid = threadIdx.x;
    const int bx = blockIdx.x;   // N tile 0..11
    const int by = blockIdx.y;   // M tile 0..1023
    const int tr = tid >> 4, tc = tid & 15;
    const int rowA0 = by * 128;
    const int colB0 = bx * 128;
    const int iA_r = tid >> 2;          // 0..63
    const int iA_c = (tid & 3) * 4;     // 0,4,8,12
    const int iB_r = tid >> 5;          // 0..7
    const int iB_c = (tid & 31) * 4;    // 0..124

    float acc[8][8];
#pragma unroll
    for (int i = 0; i < 8; i++)
#pragma unroll
        for (int j = 0; j < 8; j++) acc[i][j] = 0.f;

    for (int kt = 0; kt < II; kt += 16) {
        // A tile 128x16 -> As[k][m] (transposed)
#pragma unroll
        for (int off = 0; off < 128; off += 64) {
            float4 v = *(const float4*)&A[(size_t)(rowA0 + iA_r + off) * II + kt + iA_c];
            As[(iA_c + 0) * 132 + iA_r + off] = v.x;
            As[(iA_c + 1) * 132 + iA_r + off] = v.y;
            As[(iA_c + 2) * 132 + iA_r + off] = v.z;
            As[(iA_c + 3) * 132 + iA_r + off] = v.w;
        }
        // B tile 16x128
#pragma unroll
        for (int off = 0; off < 16; off += 8) {
            float4 v = *(const float4*)&Bm[(size_t)(kt + iB_r + off) * GG + colB0 + iB_c];
            *(float4*)&Bs[(iB_r + off) * 132 + iB_c] = v;
        }
        __syncthreads();
#pragma unroll
        for (int k = 0; k < 16; k++) {
            float rm[8], rn[8];
            *(float4*)&rm[0] = *(const float4*)&As[k * 132 + tr * 8];
            *(float4*)&rm[4] = *(const float4*)&As[k * 132 + tr * 8 + 4];
            *(float4*)&rn[0] = *(const float4*)&Bs[k * 132 + tc * 8];
            *(float4*)&rn[4] = *(const float4*)&Bs[k * 132 + tc * 8 + 4];
#pragma unroll
            for (int i = 0; i < 8; i++)
#pragma unroll
                for (int j = 0; j < 8; j++) acc[i][j] += rm[i] * rn[j];
        }
        __syncthreads();
    }
    // epilogue: +bias, write to g_xproj
#pragma unroll
    for (int i = 0; i < 8; i++) {
        int row = rowA0 + tr * 8 + i;
#pragma unroll
        for (int j = 0; j < 8; j += 4) {
            int col = colB0 + tc * 8 + j;
            float4 bv = *(const float4*)&bias[col];
            float4 o;
            o.x = acc[i][j + 0] + bv.x;
            o.y = acc[i][j + 1] + bv.y;
            o.z = acc[i][j + 2] + bv.z;
            o.w = acc[i][j + 3] + bv.w;
            *(float4*)&g_xproj[(size_t)row * GG + col] = o;
        }
    }
}

// ---------------- grid barrier (sense-reversing, state-clean across replays) ----------------
__device__ __forceinline__ void gridbar(unsigned nctas) {
    __syncthreads();
    if (threadIdx.x == 0) {
        __threadfence();
        unsigned gen = g_gen;
        if (atomicAdd(&g_cnt, 1u) == nctas - 1) {
            g_cnt = 0;
            __threadfence();
            g_gen = gen + 1;
        } else {
            while (g_gen == gen) { }
        }
    }
    __syncthreads();
}

// ---------------- Phase 2: persistent recurrence kernel ----------------
// grid = 128 CTAs = 4 batch-groups(16 rows) x 32 feature-groups(16 features).
// Each CTA computes gates for its 16 rows x (16 feats x 3 gates = 48 cols),
// K = 512 (full h), U slice resident in smem for whole kernel.
// One grid barrier per timestep; h ping-pongs between g_hA/g_hB via .cg ld/st.
constexpr int SM_U   = 48 * 516;  // U slice, [c][k], padded rows
constexpr int SM_H   = 16 * 516;  // h slice, [r][k], padded rows
constexpr int SM_RED = 8 * 768;   // per-warp partials
constexpr int SMEM_BYTES = (SM_U + SM_H + SM_RED) * 4;  // 156,672 B

__global__ __launch_bounds__(256, 1) void lstm_rec(const float* __restrict__ U,
                                                   float* __restrict__ out) {
    extern __shared__ float sm[];
    float* U_s = sm;
    float* h_s = sm + SM_U;
    float* red = sm + SM_U + SM_H;

    const int tid = threadIdx.x;
    const int bid = blockIdx.x;       // 0..127
    const int mg = bid >> 5;          // 0..3  batch group
    const int ng = bid & 31;          // 0..31 feature group
    const int r0 = mg * 16;           // batch row base
    const int n16 = ng * 16;          // feature base

    // Load U slice: local col c = gate*16 + f  ->  global col = gate*512 + n16 + f
    for (int idx = tid; idx < 48 * 512; idx += 256) {
        int c = idx % 48;
        int k = idx / 48;
        int colg = (c >> 4) * HH + n16 + (c & 15);
        U_s[c * 516 + k] = U[(size_t)k * GG + colg];
    }

    const int lane = tid & 31, w = tid >> 5;  // 8 warps: k-split of 64 each
    const int rg = lane >> 3;                 // rows 4*rg .. 4*rg+3
    const int cg = lane & 7;                  // cols 6*cg .. 6*cg+5
    const int kbase = w * 64;

    // Per-thread reduction outputs: o = tid + s*256 (0..767)
    int o_r[3], o_colg[3];
#pragma unroll
    for (int s2 = 0; s2 < 3; s2++) {
        int o = tid + s2 * 256;
        int r = o / 48, c = o % 48;
        o_r[s2] = r;
        o_colg[s2] = (c >> 4) * HH + n16 + (c & 15);
    }

    float* outh = out + (size_t)BB * SS * HH;
    float* outc = outh + BB * HH;

    __syncthreads();  // U_s ready

    for (int t = 0; t < SS; ++t) {
        const float* hprev = (t & 1) ? g_hB : g_hA;
        float* hnext = (t & 1) ? g_hA : g_hB;

        // Prefetch x_proj for this step (hides DRAM latency behind the matmul)
        float xp[3];
#pragma unroll
        for (int s2 = 0; s2 < 3; s2++)
            xp[s2] = __ldg(&g_xproj[((size_t)(r0 + o_r[s2]) * SS + t) * GG + o_colg[s2]]);

        // Load h slice (16x512) into smem. L1 is incoherent -> .cg loads.
        if (t == 0) {
            for (int q = tid; q < SM_H; q += 256) h_s[q] = 0.f;
        } else {
            for (int q = tid; q < 2048; q += 256) {
                int r = q >> 7, k4 = q & 127;
                float4 v = __ldcg((const float4*)&hprev[(r0 + r) * HH + k4 * 4]);
                *(float4*)&h_s[r * 516 + k4 * 4] = v;
            }
        }
        __syncthreads();

        // gates partial: acc[4][6] over this warp's 64-deep K chunk
        float acc[4][6];
#pragma unroll
        for (int i = 0; i < 4; i++)
#pragma unroll
            for (int j = 0; j < 6; j++) acc[i][j] = 0.f;

#pragma unroll 4
        for (int kk = 0; kk < 64; kk += 4) {
            int k = kbase + kk;
            float4 h0 = *(const float4*)&h_s[(4 * rg + 0) * 516 + k];
            float4 h1 = *(const float4*)&h_s[(4 * rg + 1) * 516 + k];
            float4 h2 = *(const float4*)&h_s[(4 * rg + 2) * 516 + k];
            float4 h3 = *(const float4*)&h_s[(4 * rg + 3) * 516 + k];
#pragma unroll
            for (int j = 0; j < 6; j++) {
                float4 u = *(const float4*)&U_s[(6 * cg + j) * 516 + k];
                acc[0][j] += h0.x * u.x + h0.y * u.y + h0.z * u.z + h0.w * u.w;
                acc[1][j] += h1.x * u.x + h1.y * u.y + h1.z * u.z + h1.w * u.w;
                acc[2][j] += h2.x * u.x + h2.y * u.y + h2.z * u.z + h2.w * u.w;
                acc[3][j] += h3.x * u.x + h3.y * u.y + h3.z * u.z + h3.w * u.w;
            }
        }

        // write per-warp partials
#pragma unroll
        for (int i = 0; i < 4; i++)
#pragma unroll
            for (int j = 0; j < 6; j++)
                red[w * 768 + (4 * rg + i) * 48 + (6 * cg + j)] = acc[i][j];
        __syncthreads();

        // k-reduce 8 warps + x_proj -> gates in red[0..767]
#pragma unroll
        for (int s2 = 0; s2 < 3; s2++) {
            int o = tid + s2 * 256;
            float v = xp[s2];
#pragma unroll
            for (int w2 = 0; w2 < 8; w2++) v += red[w2 * 768 + o];
            red[o] = v;  // each o owned by exactly one thread -> no race
        }
        __syncthreads();

        // elementwise LSTM-noforget: one (row, feature) per thread (16x16=256)
        {
            int r = tid >> 4, f = tid & 15;
            float gi = red[r * 48 + f];
            float gg = red[r * 48 + 16 + f];
            float go = red[r * 48 + 32 + f];
            float iv = 1.f / (1.f + __expf(-gi));
            float gv = tanhf(gg);
            float ov = 1.f / (1.f + __expf(-go));
            float cv = iv * gv;                 // no-forget: c = i*g
            float hv = ov * tanhf(cv);
            int b = r0 + r, jg = n16 + f;
            __stcg(&hnext[b * HH + jg], hv);    // bypass L1 (cross-CTA visibility)
            out[((size_t)b * SS + t) * HH + jg] = hv;   // hidden_seq
            if (t == SS - 1) {
                outh[b * HH + jg] = hv;         // h_f
                outc[b * HH + jg] = cv;         // c_f
            }
        }

        if (t != SS - 1) gridbar(128);
    }
}

// ---------------- launch ----------------
extern "C" void kernel_launch(void* const* d_in, const int* in_sizes, int n_in,
                              void* d_out, int out_size) {
    const float* x    = (const float*)d_in[0];
    const float* W    = (const float*)d_in[1];
    const float* U    = (const float*)d_in[2];
    const float* bias = (const float*)d_in[3];
    float* out = (float*)d_out;

    cudaFuncSetAttribute(lstm_rec, cudaFuncAttributeMaxDynamicSharedMemorySize, SMEM_BYTES);

    dim3 g1(GG / 128, (BB * SS) / 128);   // 12 x 1024
    gemm_xw<<<g1, 256>>>(x, W, bias);
    lstm_rec<<<128, 256, SMEM_BYTES>>>(U, out);
}